// round 1
// baseline (speedup 1.0000x reference)
#include <cuda_runtime.h>

#define B_ 4
#define N_ 2048
#define C_ 1024
#define SCALE_ 0.03125f   // 1/sqrt(1024)

// Scratch (allocation-free rule: __device__ globals)
__device__ float g_Q[(long)B_ * N_ * C_];
__device__ float g_K[(long)B_ * N_ * C_];
__device__ float g_V[(long)B_ * N_ * C_];

#define BM 128
#define BN 128
#define BK 8
#define TM 8
#define TN 8
// 256 threads = 16x16 thread grid, each owns an 8x8 microtile.

// ---------------------------------------------------------------------------
// NT GEMM: C[m,n] = scale * sum_k A[m,k] * B[n,k] + bias[n]
// A: [M,K] row-major, Bm: [Nd,K] row-major. All dims multiples of tile sizes.
// Batched via blockIdx.z with element strides.
// ---------------------------------------------------------------------------
__global__ __launch_bounds__(256) void gemm_nt_kernel(
    const float* __restrict__ A, const float* __restrict__ Bm,
    const float* __restrict__ bias, float* __restrict__ C,
    int M, int Nd, int K, float scale,
    long long strideA, long long strideB, long long strideC)
{
    __shared__ float As[BK][BM];
    __shared__ float Bs[BK][BN];

    const float* Ab = A + (long long)blockIdx.z * strideA + (long long)blockIdx.y * BM * K;
    const float* Bb = Bm + (long long)blockIdx.z * strideB + (long long)blockIdx.x * BN * K;
    float* Cb = C + (long long)blockIdx.z * strideC;

    const int tid  = threadIdx.x;
    const int tx   = tid & 15;          // 0..15  -> N direction
    const int ty   = tid >> 4;          // 0..15  -> M direction
    const int lrow = tid >> 1;          // 0..127 load row
    const int lcol = (tid & 1) * 4;     // 0 or 4 load col (float4)

    float acc[TM][TN];
#pragma unroll
    for (int i = 0; i < TM; i++)
#pragma unroll
        for (int j = 0; j < TN; j++) acc[i][j] = 0.f;

    for (int k0 = 0; k0 < K; k0 += BK) {
        float4 av = *(const float4*)(Ab + (long long)lrow * K + k0 + lcol);
        float4 bv = *(const float4*)(Bb + (long long)lrow * K + k0 + lcol);
        As[lcol + 0][lrow] = av.x; As[lcol + 1][lrow] = av.y;
        As[lcol + 2][lrow] = av.z; As[lcol + 3][lrow] = av.w;
        Bs[lcol + 0][lrow] = bv.x; Bs[lcol + 1][lrow] = bv.y;
        Bs[lcol + 2][lrow] = bv.z; Bs[lcol + 3][lrow] = bv.w;
        __syncthreads();

#pragma unroll
        for (int k = 0; k < BK; k++) {
            float4 a0 = *(const float4*)&As[k][ty * TM];
            float4 a1 = *(const float4*)&As[k][ty * TM + 4];
            float4 b0 = *(const float4*)&Bs[k][tx * TN];
            float4 b1 = *(const float4*)&Bs[k][tx * TN + 4];
            float a[8] = {a0.x, a0.y, a0.z, a0.w, a1.x, a1.y, a1.z, a1.w};
            float b[8] = {b0.x, b0.y, b0.z, b0.w, b1.x, b1.y, b1.z, b1.w};
#pragma unroll
            for (int i = 0; i < TM; i++)
#pragma unroll
                for (int j = 0; j < TN; j++) acc[i][j] += a[i] * b[j];
        }
        __syncthreads();
    }

    const int colBase = blockIdx.x * BN + tx * TN;
    float bb[TN];
#pragma unroll
    for (int j = 0; j < TN; j++) bb[j] = bias ? bias[colBase + j] : 0.f;

#pragma unroll
    for (int i = 0; i < TM; i++) {
        long long row = (long long)blockIdx.y * BM + ty * TM + i;
        float4 v0, v1;
        v0.x = scale * acc[i][0] + bb[0]; v0.y = scale * acc[i][1] + bb[1];
        v0.z = scale * acc[i][2] + bb[2]; v0.w = scale * acc[i][3] + bb[3];
        v1.x = scale * acc[i][4] + bb[4]; v1.y = scale * acc[i][5] + bb[5];
        v1.z = scale * acc[i][6] + bb[6]; v1.w = scale * acc[i][7] + bb[7];
        *(float4*)(Cb + row * Nd + colBase)     = v0;
        *(float4*)(Cb + row * Nd + colBase + 4) = v1;
    }
}

// ---------------------------------------------------------------------------
// NN GEMM: C[m,n] = sum_k A[m,k] * Bm[k,n]
// A: [M,K] row-major, Bm: [K,Nd] row-major.
// ---------------------------------------------------------------------------
__global__ __launch_bounds__(256) void gemm_nn_kernel(
    const float* __restrict__ A, const float* __restrict__ Bm,
    float* __restrict__ C,
    int M, int Nd, int K,
    long long strideA, long long strideB, long long strideC)
{
    __shared__ float As[BK][BM];
    __shared__ float Bs[BK][BN];

    const float* Ab = A + (long long)blockIdx.z * strideA + (long long)blockIdx.y * BM * K;
    const float* Bb = Bm + (long long)blockIdx.z * strideB + (long long)blockIdx.x * BN;
    float* Cb = C + (long long)blockIdx.z * strideC;

    const int tid  = threadIdx.x;
    const int tx   = tid & 15;
    const int ty   = tid >> 4;
    const int lrow = tid >> 1;          // A tile row 0..127
    const int lcol = (tid & 1) * 4;     // A tile col 0 or 4
    const int brow = tid >> 5;          // B tile row 0..7
    const int bcol = (tid & 31) * 4;    // B tile col 0..124

    float acc[TM][TN];
#pragma unroll
    for (int i = 0; i < TM; i++)
#pragma unroll
        for (int j = 0; j < TN; j++) acc[i][j] = 0.f;

    for (int k0 = 0; k0 < K; k0 += BK) {
        float4 av = *(const float4*)(Ab + (long long)lrow * K + k0 + lcol);
        As[lcol + 0][lrow] = av.x; As[lcol + 1][lrow] = av.y;
        As[lcol + 2][lrow] = av.z; As[lcol + 3][lrow] = av.w;
        float4 bv = *(const float4*)(Bb + (long long)(k0 + brow) * Nd + bcol);
        *(float4*)&Bs[brow][bcol] = bv;
        __syncthreads();

#pragma unroll
        for (int k = 0; k < BK; k++) {
            float4 a0 = *(const float4*)&As[k][ty * TM];
            float4 a1 = *(const float4*)&As[k][ty * TM + 4];
            float4 b0 = *(const float4*)&Bs[k][tx * TN];
            float4 b1 = *(const float4*)&Bs[k][tx * TN + 4];
            float a[8] = {a0.x, a0.y, a0.z, a0.w, a1.x, a1.y, a1.z, a1.w};
            float b[8] = {b0.x, b0.y, b0.z, b0.w, b1.x, b1.y, b1.z, b1.w};
#pragma unroll
            for (int i = 0; i < TM; i++)
#pragma unroll
                for (int j = 0; j < TN; j++) acc[i][j] += a[i] * b[j];
        }
        __syncthreads();
    }

    const int colBase = blockIdx.x * BN + tx * TN;
#pragma unroll
    for (int i = 0; i < TM; i++) {
        long long row = (long long)blockIdx.y * BM + ty * TM + i;
        float4 v0, v1;
        v0.x = acc[i][0]; v0.y = acc[i][1]; v0.z = acc[i][2]; v0.w = acc[i][3];
        v1.x = acc[i][4]; v1.y = acc[i][5]; v1.z = acc[i][6]; v1.w = acc[i][7];
        *(float4*)(Cb + row * Nd + colBase)     = v0;
        *(float4*)(Cb + row * Nd + colBase + 4) = v1;
    }
}

// ---------------------------------------------------------------------------
// Row softmax, in place. One block per row (N_ = 2048 cols, 256 threads).
// ---------------------------------------------------------------------------
__global__ __launch_bounds__(256) void softmax_rows_kernel(float* __restrict__ att)
{
    float* p = att + (long long)blockIdx.x * N_;
    const int tid = threadIdx.x;
    __shared__ float red[8];

    // max
    float m = -3.0e38f;
    for (int i = tid; i < N_; i += 256) m = fmaxf(m, p[i]);
#pragma unroll
    for (int o = 16; o > 0; o >>= 1) m = fmaxf(m, __shfl_xor_sync(0xffffffffu, m, o));
    if ((tid & 31) == 0) red[tid >> 5] = m;
    __syncthreads();
    m = red[0];
#pragma unroll
    for (int i = 1; i < 8; i++) m = fmaxf(m, red[i]);
    __syncthreads();

    // exp + sum
    float s = 0.f;
    for (int i = tid; i < N_; i += 256) {
        float e = __expf(p[i] - m);
        p[i] = e;
        s += e;
    }
#pragma unroll
    for (int o = 16; o > 0; o >>= 1) s += __shfl_xor_sync(0xffffffffu, s, o);
    if ((tid & 31) == 0) red[tid >> 5] = s;
    __syncthreads();
    s = red[0];
#pragma unroll
    for (int i = 1; i < 8; i++) s += red[i];
    float inv = 1.f / s;

    for (int i = tid; i < N_; i += 256) p[i] *= inv;
}

// ---------------------------------------------------------------------------
extern "C" void kernel_launch(void* const* d_in, const int* in_sizes, int n_in,
                              void* d_out, int out_size)
{
    const float* X  = (const float*)d_in[0];
    const float* Wq = (const float*)d_in[1];
    const float* bq = (const float*)d_in[2];
    const float* Wk = (const float*)d_in[3];
    const float* bk = (const float*)d_in[4];
    const float* Wv = (const float*)d_in[5];
    const float* bv = (const float*)d_in[6];

    float* outp = (float*)d_out;                          // [B, N, C]
    float* att  = outp + (long long)B_ * N_ * C_;         // [B, N, N]

    float *Q, *K, *V;
    cudaGetSymbolAddress((void**)&Q, g_Q);
    cudaGetSymbolAddress((void**)&K, g_K);
    cudaGetSymbolAddress((void**)&V, g_V);

    const long long sNC = (long long)N_ * C_;
    const long long sNN = (long long)N_ * N_;

    // 1) QKV projections: y = X @ W^T + b   (NT, M = B*N = 8192, Nd = K = 1024)
    {
        dim3 grid(C_ / BN, (B_ * N_) / BM, 1);
        gemm_nt_kernel<<<grid, 256>>>(X, Wq, bq, Q, B_ * N_, C_, C_, 1.0f, 0, 0, 0);
        gemm_nt_kernel<<<grid, 256>>>(X, Wk, bk, K, B_ * N_, C_, C_, 1.0f, 0, 0, 0);
        gemm_nt_kernel<<<grid, 256>>>(X, Wv, bv, V, B_ * N_, C_, C_, 1.0f, 0, 0, 0);
    }

    // 2) scores = Q @ K^T * scale   (NT batched over B)
    {
        dim3 grid(N_ / BN, N_ / BM, B_);
        gemm_nt_kernel<<<grid, 256>>>(Q, K, nullptr, att, N_, N_, C_, SCALE_,
                                      sNC, sNC, sNN);
    }

    // 3) softmax rows, in place in d_out's attention region
    softmax_rows_kernel<<<B_ * N_, 256>>>(att);

    // 4) out = attention @ V   (NN batched over B)
    {
        dim3 grid(C_ / BN, N_ / BM, B_);
        gemm_nn_kernel<<<grid, 256>>>(att, V, outp, N_, C_, N_,
                                      sNN, sNC, sNC);
    }
}

// round 3
// speedup vs baseline: 2.4109x; 2.4109x over previous
#include <cuda_runtime.h>
#include <cuda_bf16.h>
#include <cstdint>

#define SCALE_ 0.03125f   // 1/sqrt(1024)

// ---------------- bf16-split scratch (device globals; no allocation) -------
__device__ __nv_bfloat16 g_Xhi[8192*1024];
__device__ __nv_bfloat16 g_Xlo[8192*1024];
__device__ __nv_bfloat16 g_Wqhi[1024*1024];
__device__ __nv_bfloat16 g_Wqlo[1024*1024];
__device__ __nv_bfloat16 g_Wkhi[1024*1024];
__device__ __nv_bfloat16 g_Wklo[1024*1024];
__device__ __nv_bfloat16 g_Wvhi[1024*1024];
__device__ __nv_bfloat16 g_Wvlo[1024*1024];
__device__ __nv_bfloat16 g_Qhi[8192*1024];
__device__ __nv_bfloat16 g_Qlo[8192*1024];
__device__ __nv_bfloat16 g_Khi[8192*1024];
__device__ __nv_bfloat16 g_Klo[8192*1024];
__device__ __nv_bfloat16 g_Vthi[1024*8192];   // V^T: [C, B*N]
__device__ __nv_bfloat16 g_Vtlo[1024*8192];
__device__ __nv_bfloat16 g_AThi[16777216];    // attention split [B,N,N]
__device__ __nv_bfloat16 g_ATlo[16777216];

// ---------------- PTX helpers ----------------------------------------------
__device__ __forceinline__ uint32_t smem_u32(const void* p) {
    uint32_t a;
    asm("{ .reg .u64 t; cvta.to.shared.u64 t, %1; cvt.u32.u64 %0, t; }"
        : "=r"(a) : "l"(p));
    return a;
}

__device__ __forceinline__ void cpa16(uint32_t dst, const void* src) {
    asm volatile("cp.async.cg.shared.global [%0], [%1], 16;" :: "r"(dst), "l"(src));
}
#define CP_COMMIT() asm volatile("cp.async.commit_group;" ::: "memory")

__device__ __forceinline__ void ldm4(uint32_t* r, uint32_t a) {
    asm volatile("ldmatrix.sync.aligned.m8n8.x4.shared.b16 {%0,%1,%2,%3}, [%4];"
        : "=r"(r[0]), "=r"(r[1]), "=r"(r[2]), "=r"(r[3]) : "r"(a));
}

__device__ __forceinline__ void mma16816(float* d, const uint32_t* a,
                                         uint32_t b0, uint32_t b1) {
    asm volatile(
        "mma.sync.aligned.m16n8k16.row.col.f32.bf16.bf16.f32 "
        "{%0,%1,%2,%3}, {%4,%5,%6,%7}, {%8,%9}, {%0,%1,%2,%3};"
        : "+f"(d[0]), "+f"(d[1]), "+f"(d[2]), "+f"(d[3])
        : "r"(a[0]), "r"(a[1]), "r"(a[2]), "r"(a[3]), "r"(b0), "r"(b1));
}

// ---------------- GEMM kernel ----------------------------------------------
// C[m,n] = sum_k A[m,k]*B[n,k]  (NT, 3-term bf16 split). Tile 128x128, BK=32.
// MODE 0: out = acc + bias[n] -> bf16 hi/lo
// MODE 1: out = acc + bias[m] -> bf16 hi/lo
// MODE 2: out = acc * scale   -> fp32
// MODE 3: out = acc * scale   -> fp32
#define BM 128
#define BN 128
#define BKt 32
#define TILE_STRIDE 80                       // bytes per 32-elem bf16 row (+16B pad)
#define SUB_BYTES (128*TILE_STRIDE)          // 10240 per sub-tile
#define STAGE_BYTES (4*SUB_BYTES)            // Ahi Alo Bhi Blo = 40960
#define GEMM_SMEM (3*STAGE_BYTES)            // 122880

__device__ __forceinline__ void load_tile(
    uint32_t stbase,
    const __nv_bfloat16* pAh, const __nv_bfloat16* pAl,
    const __nv_bfloat16* pBh, const __nv_bfloat16* pBl,
    long long ldA, long long ldB, int k0, int tid)
{
#pragma unroll
    for (int t = 0; t < 2; t++) {
        int id = tid + t * 256;
        int r = id >> 2, c = id & 3;
        uint32_t doff = (uint32_t)r * TILE_STRIDE + c * 16;
        long long soA = (long long)r * ldA + k0 + c * 8;
        long long soB = (long long)r * ldB + k0 + c * 8;
        cpa16(stbase + doff,                 pAh + soA);
        cpa16(stbase + SUB_BYTES + doff,     pAl + soA);
        cpa16(stbase + 2*SUB_BYTES + doff,   pBh + soB);
        cpa16(stbase + 3*SUB_BYTES + doff,   pBl + soB);
    }
}

template<int MODE>
__global__ __launch_bounds__(256) void mm_kernel(
    const __nv_bfloat16* __restrict__ Ahi, const __nv_bfloat16* __restrict__ Alo,
    long long ldA, long long strideA,
    const __nv_bfloat16* __restrict__ Bhi, const __nv_bfloat16* __restrict__ Blo,
    long long ldB, long long strideB,
    const float* __restrict__ bias,
    float* __restrict__ outF,
    __nv_bfloat16* __restrict__ outHi, __nv_bfloat16* __restrict__ outLo,
    long long ldC, long long strideC,
    int Ksz, float scale)
{
    extern __shared__ char smem[];
    const uint32_t sb = smem_u32(smem);
    const int tid = threadIdx.x;
    const int wid = tid >> 5, lane = tid & 31;
    const int wm = wid >> 2, wn = wid & 3;        // 2 x 4 warp grid
    const int g8 = lane & 7, quad = lane >> 3;
    const int g = lane >> 2, tg = lane & 3;

    const long long bz = blockIdx.z;
    const long long tileM = (long long)blockIdx.y * BM;
    const long long tileN = (long long)blockIdx.x * BN;
    const __nv_bfloat16* pAh = Ahi + bz * strideA + tileM * ldA;
    const __nv_bfloat16* pAl = Alo + bz * strideA + tileM * ldA;
    const __nv_bfloat16* pBh = Bhi + bz * strideB + tileN * ldB;
    const __nv_bfloat16* pBl = Blo + bz * strideB + tileN * ldB;

    float acc[4][4][4];
#pragma unroll
    for (int i = 0; i < 4; i++)
#pragma unroll
        for (int j = 0; j < 4; j++)
#pragma unroll
            for (int c = 0; c < 4; c++) acc[i][j][c] = 0.f;

    const int KT = Ksz / BKt;

    // prologue: 2 stages in flight
    load_tile(sb + 0*STAGE_BYTES, pAh, pAl, pBh, pBl, ldA, ldB, 0, tid);
    CP_COMMIT();
    load_tile(sb + 1*STAGE_BYTES, pAh, pAl, pBh, pBl, ldA, ldB, BKt, tid);
    CP_COMMIT();

    // per-thread ldmatrix base offsets (row-padded layout, stride 80B)
    const uint32_t aBase = (uint32_t)(wm*64 + g8 + ((quad & 1) ? 8 : 0)) * TILE_STRIDE
                         + ((quad & 2) ? 16 : 0);
    const uint32_t bBase = (uint32_t)(wn*32 + g8 + ((quad & 2) ? 8 : 0)) * TILE_STRIDE
                         + ((quad & 1) ? 16 : 0);

    for (int kt = 0; kt < KT; kt++) {
        if (kt < KT - 1) asm volatile("cp.async.wait_group 1;" ::: "memory");
        else             asm volatile("cp.async.wait_group 0;" ::: "memory");
        __syncthreads();
        if (kt + 2 < KT) {
            load_tile(sb + ((kt + 2) % 3) * STAGE_BYTES, pAh, pAl, pBh, pBl,
                      ldA, ldB, (kt + 2) * BKt, tid);
            CP_COMMIT();
        }
        const uint32_t base = sb + (kt % 3) * STAGE_BYTES;
#pragma unroll
        for (int ks = 0; ks < 2; ks++) {
            uint32_t ah[4][4], al[4][4], bh[2][4], bl[2][4];
#pragma unroll
            for (int i = 0; i < 4; i++)
                ldm4(ah[i], base + aBase + i * (16*TILE_STRIDE) + ks * 32);
#pragma unroll
            for (int j = 0; j < 2; j++)
                ldm4(bh[j], base + 2*SUB_BYTES + bBase + j * (16*TILE_STRIDE) + ks * 32);
            // hi * hi
#pragma unroll
            for (int i = 0; i < 4; i++)
#pragma unroll
                for (int j = 0; j < 4; j++)
                    mma16816(acc[i][j], ah[i], bh[j>>1][(j&1)*2], bh[j>>1][(j&1)*2+1]);
            // hi * lo
#pragma unroll
            for (int j = 0; j < 2; j++)
                ldm4(bl[j], base + 3*SUB_BYTES + bBase + j * (16*TILE_STRIDE) + ks * 32);
#pragma unroll
            for (int i = 0; i < 4; i++)
#pragma unroll
                for (int j = 0; j < 4; j++)
                    mma16816(acc[i][j], ah[i], bl[j>>1][(j&1)*2], bl[j>>1][(j&1)*2+1]);
            // lo * hi
#pragma unroll
            for (int i = 0; i < 4; i++)
                ldm4(al[i], base + SUB_BYTES + aBase + i * (16*TILE_STRIDE) + ks * 32);
#pragma unroll
            for (int i = 0; i < 4; i++)
#pragma unroll
                for (int j = 0; j < 4; j++)
                    mma16816(acc[i][j], al[i], bh[j>>1][(j&1)*2], bh[j>>1][(j&1)*2+1]);
        }
    }

    // ---------------- epilogue ----------------
    const long long rowBase = tileM + wm * 64;
    const long long colBase = tileN + wn * 32;
    const long long cOff = bz * strideC;
#pragma unroll
    for (int i = 0; i < 4; i++) {
#pragma unroll
        for (int j = 0; j < 4; j++) {
            long long r0 = rowBase + i * 16 + g;
            long long c0 = colBase + j * 8 + 2 * tg;
#pragma unroll
            for (int h = 0; h < 2; h++) {
                long long r = r0 + h * 8;
                float f0 = acc[i][j][2*h + 0];
                float f1 = acc[i][j][2*h + 1];
                long long off = cOff + r * ldC + c0;
                if (MODE >= 2) {
                    float2 v; v.x = f0 * scale; v.y = f1 * scale;
                    *(float2*)(outF + off) = v;
                } else {
                    if (MODE == 0) { f0 += bias[c0]; f1 += bias[c0 + 1]; }
                    else           { float bb = bias[r]; f0 += bb; f1 += bb; }
                    __nv_bfloat16 h0 = __float2bfloat16(f0);
                    __nv_bfloat16 h1 = __float2bfloat16(f1);
                    __nv_bfloat16 l0 = __float2bfloat16(f0 - __bfloat162float(h0));
                    __nv_bfloat16 l1 = __float2bfloat16(f1 - __bfloat162float(h1));
                    uint32_t hp = (uint32_t)__bfloat16_as_ushort(h0) |
                                  ((uint32_t)__bfloat16_as_ushort(h1) << 16);
                    uint32_t lp = (uint32_t)__bfloat16_as_ushort(l0) |
                                  ((uint32_t)__bfloat16_as_ushort(l1) << 16);
                    *(uint32_t*)(outHi + off) = hp;
                    *(uint32_t*)(outLo + off) = lp;
                }
            }
        }
    }
}

// ---------------- split fp32 -> bf16 hi/lo ---------------------------------
__global__ __launch_bounds__(256) void split_kernel(
    const float4* __restrict__ src, uint2* __restrict__ hi, uint2* __restrict__ lo, int n4)
{
    int i = blockIdx.x * 256 + threadIdx.x;
    if (i >= n4) return;
    float4 v = src[i];
    float f[4] = {v.x, v.y, v.z, v.w};
    uint32_t hh[2], ll[2];
#pragma unroll
    for (int j = 0; j < 2; j++) {
        __nv_bfloat16 h0 = __float2bfloat16(f[2*j]);
        __nv_bfloat16 h1 = __float2bfloat16(f[2*j+1]);
        __nv_bfloat16 l0 = __float2bfloat16(f[2*j]   - __bfloat162float(h0));
        __nv_bfloat16 l1 = __float2bfloat16(f[2*j+1] - __bfloat162float(h1));
        hh[j] = (uint32_t)__bfloat16_as_ushort(h0) | ((uint32_t)__bfloat16_as_ushort(h1) << 16);
        ll[j] = (uint32_t)__bfloat16_as_ushort(l0) | ((uint32_t)__bfloat16_as_ushort(l1) << 16);
    }
    hi[i] = make_uint2(hh[0], hh[1]);
    lo[i] = make_uint2(ll[0], ll[1]);
}

// ---------------- softmax rows, in-place, + bf16 split ---------------------
__global__ __launch_bounds__(256) void softmax_split_kernel(
    float* __restrict__ att, __nv_bfloat16* __restrict__ ahi, __nv_bfloat16* __restrict__ alo)
{
    __shared__ float row[2048];
    __shared__ float red[8];
    const long long base = (long long)blockIdx.x * 2048;
    float* p = att + base;
    const int tid = threadIdx.x;

    float m = -3.0e38f;
    for (int i = tid; i < 2048; i += 256) { float v = p[i]; row[i] = v; m = fmaxf(m, v); }
#pragma unroll
    for (int o = 16; o > 0; o >>= 1) m = fmaxf(m, __shfl_xor_sync(0xffffffffu, m, o));
    if ((tid & 31) == 0) red[tid >> 5] = m;
    __syncthreads();
    m = red[0];
#pragma unroll
    for (int i = 1; i < 8; i++) m = fmaxf(m, red[i]);
    __syncthreads();

    float s = 0.f;
    for (int i = tid; i < 2048; i += 256) { float e = __expf(row[i] - m); row[i] = e; s += e; }
#pragma unroll
    for (int o = 16; o > 0; o >>= 1) s += __shfl_xor_sync(0xffffffffu, s, o);
    if ((tid & 31) == 0) red[tid >> 5] = s;
    __syncthreads();
    s = red[0];
#pragma unroll
    for (int i = 1; i < 8; i++) s += red[i];
    const float inv = 1.f / s;

    for (int i = tid; i < 2048; i += 256) {
        float v = row[i] * inv;
        p[i] = v;
        __nv_bfloat16 h = __float2bfloat16(v);
        ahi[base + i] = h;
        alo[base + i] = __float2bfloat16(v - __bfloat162float(h));
    }
}

// ---------------------------------------------------------------------------
extern "C" void kernel_launch(void* const* d_in, const int* in_sizes, int n_in,
                              void* d_out, int out_size)
{
    const float* X  = (const float*)d_in[0];
    const float* Wq = (const float*)d_in[1];
    const float* bq = (const float*)d_in[2];
    const float* Wk = (const float*)d_in[3];
    const float* bk = (const float*)d_in[4];
    const float* Wv = (const float*)d_in[5];
    const float* bv = (const float*)d_in[6];

    float* outp = (float*)d_out;                      // [4,2048,1024]
    float* att  = outp + 8388608ll;                   // [4,2048,2048]

    __nv_bfloat16 *Xhi, *Xlo, *Wqh, *Wql, *Wkh, *Wkl, *Wvh, *Wvl;
    __nv_bfloat16 *Qhi, *Qlo, *Khi, *Klo, *Vth, *Vtl, *Ahi, *Alo;
    cudaGetSymbolAddress((void**)&Xhi, g_Xhi);  cudaGetSymbolAddress((void**)&Xlo, g_Xlo);
    cudaGetSymbolAddress((void**)&Wqh, g_Wqhi); cudaGetSymbolAddress((void**)&Wql, g_Wqlo);
    cudaGetSymbolAddress((void**)&Wkh, g_Wkhi); cudaGetSymbolAddress((void**)&Wkl, g_Wklo);
    cudaGetSymbolAddress((void**)&Wvh, g_Wvhi); cudaGetSymbolAddress((void**)&Wvl, g_Wvlo);
    cudaGetSymbolAddress((void**)&Qhi, g_Qhi);  cudaGetSymbolAddress((void**)&Qlo, g_Qlo);
    cudaGetSymbolAddress((void**)&Khi, g_Khi);  cudaGetSymbolAddress((void**)&Klo, g_Klo);
    cudaGetSymbolAddress((void**)&Vth, g_Vthi); cudaGetSymbolAddress((void**)&Vtl, g_Vtlo);
    cudaGetSymbolAddress((void**)&Ahi, g_AThi); cudaGetSymbolAddress((void**)&Alo, g_ATlo);

    cudaFuncSetAttribute(mm_kernel<0>, cudaFuncAttributeMaxDynamicSharedMemorySize, GEMM_SMEM);
    cudaFuncSetAttribute(mm_kernel<1>, cudaFuncAttributeMaxDynamicSharedMemorySize, GEMM_SMEM);
    cudaFuncSetAttribute(mm_kernel<2>, cudaFuncAttributeMaxDynamicSharedMemorySize, GEMM_SMEM);
    cudaFuncSetAttribute(mm_kernel<3>, cudaFuncAttributeMaxDynamicSharedMemorySize, GEMM_SMEM);

    // 1) split inputs to bf16 hi/lo
    split_kernel<<<8192, 256>>>((const float4*)X,  (uint2*)Xhi, (uint2*)Xlo, 2097152);
    split_kernel<<<1024, 256>>>((const float4*)Wq, (uint2*)Wqh, (uint2*)Wql, 262144);
    split_kernel<<<1024, 256>>>((const float4*)Wk, (uint2*)Wkh, (uint2*)Wkl, 262144);
    split_kernel<<<1024, 256>>>((const float4*)Wv, (uint2*)Wvh, (uint2*)Wvl, 262144);

    // 2) Q = X Wq^T + bq ; K = X Wk^T + bk   (M=8192, N=1024, K=1024)
    mm_kernel<0><<<dim3(8, 64, 1), 256, GEMM_SMEM>>>(
        Xhi, Xlo, 1024, 0, Wqh, Wql, 1024, 0, bq,
        nullptr, Qhi, Qlo, 1024, 0, 1024, 1.f);
    mm_kernel<0><<<dim3(8, 64, 1), 256, GEMM_SMEM>>>(
        Xhi, Xlo, 1024, 0, Wkh, Wkl, 1024, 0, bk,
        nullptr, Khi, Klo, 1024, 0, 1024, 1.f);

    // 3) V^T = Wv X^T + bv(row)   (M=1024 channels, N=8192 tokens, K=1024)
    mm_kernel<1><<<dim3(64, 8, 1), 256, GEMM_SMEM>>>(
        Wvh, Wvl, 1024, 0, Xhi, Xlo, 1024, 0, bv,
        nullptr, Vth, Vtl, 8192, 0, 1024, 1.f);

    // 4) scores = scale * Q K^T   (per batch: M=N=2048, K=1024) -> att fp32
    mm_kernel<2><<<dim3(16, 16, 4), 256, GEMM_SMEM>>>(
        Qhi, Qlo, 1024, 2097152ll, Khi, Klo, 1024, 2097152ll, nullptr,
        att, nullptr, nullptr, 2048, 4194304ll, 1024, SCALE_);

    // 5) softmax in place + bf16 split of attention
    softmax_split_kernel<<<8192, 256>>>(att, Ahi, Alo);

    // 6) out = att @ V  via  B = V^T  (per batch: M=2048, N=1024, K=2048)
    mm_kernel<3><<<dim3(8, 16, 4), 256, GEMM_SMEM>>>(
        Ahi, Alo, 2048, 4194304ll, Vth, Vtl, 8192, 2048ll, nullptr,
        outp, nullptr, nullptr, 1024, 2097152ll, 2048, 1.f);
}

// round 4
// speedup vs baseline: 2.8151x; 1.1676x over previous
#include <cuda_runtime.h>
#include <cuda_bf16.h>
#include <cstdint>

#define SCALE_ 0.03125f   // 1/sqrt(1024)

// ---------------- bf16-split scratch (device globals; no allocation) -------
__device__ __nv_bfloat16 g_Xhi[8192*1024];
__device__ __nv_bfloat16 g_Xlo[8192*1024];
__device__ __nv_bfloat16 g_Wqhi[1024*1024];
__device__ __nv_bfloat16 g_Wqlo[1024*1024];
__device__ __nv_bfloat16 g_Wkhi[1024*1024];
__device__ __nv_bfloat16 g_Wklo[1024*1024];
__device__ __nv_bfloat16 g_Wvhi[1024*1024];
__device__ __nv_bfloat16 g_Wvlo[1024*1024];
__device__ __nv_bfloat16 g_Qhi[8192*1024];
__device__ __nv_bfloat16 g_Qlo[8192*1024];
__device__ __nv_bfloat16 g_Khi[8192*1024];
__device__ __nv_bfloat16 g_Klo[8192*1024];
__device__ __nv_bfloat16 g_Vthi[1024*8192];   // V^T: [C, B*N]
__device__ __nv_bfloat16 g_Vtlo[1024*8192];
__device__ __nv_bfloat16 g_AThi[16777216];    // attention split [B,N,N]
__device__ __nv_bfloat16 g_ATlo[16777216];

// ---------------- PTX helpers ----------------------------------------------
__device__ __forceinline__ uint32_t smem_u32(const void* p) {
    uint32_t a;
    asm("{ .reg .u64 t; cvta.to.shared.u64 t, %1; cvt.u32.u64 %0, t; }"
        : "=r"(a) : "l"(p));
    return a;
}

__device__ __forceinline__ void cpa16(uint32_t dst, const void* src) {
    asm volatile("cp.async.cg.shared.global [%0], [%1], 16;" :: "r"(dst), "l"(src));
}
#define CP_COMMIT() asm volatile("cp.async.commit_group;" ::: "memory")

__device__ __forceinline__ void ldm4(uint32_t* r, uint32_t a) {
    asm volatile("ldmatrix.sync.aligned.m8n8.x4.shared.b16 {%0,%1,%2,%3}, [%4];"
        : "=r"(r[0]), "=r"(r[1]), "=r"(r[2]), "=r"(r[3]) : "r"(a));
}

__device__ __forceinline__ void mma16816(float* d, const uint32_t* a,
                                         uint32_t b0, uint32_t b1) {
    asm volatile(
        "mma.sync.aligned.m16n8k16.row.col.f32.bf16.bf16.f32 "
        "{%0,%1,%2,%3}, {%4,%5,%6,%7}, {%8,%9}, {%0,%1,%2,%3};"
        : "+f"(d[0]), "+f"(d[1]), "+f"(d[2]), "+f"(d[3])
        : "r"(a[0]), "r"(a[1]), "r"(a[2]), "r"(a[3]), "r"(b0), "r"(b1));
}

// ---------------- GEMM kernel ----------------------------------------------
// C[m,n] = sum_k A[m,k]*B[n,k]  (NT, 3-term bf16 split). Tile 128x128, BK=32.
// 2-stage cp.async pipeline, 2 CTAs/SM for cross-CTA overlap of LDSM vs HMMA.
// MODE 0: out = acc + bias[n] -> bf16 hi/lo
// MODE 1: out = acc + bias[m] -> bf16 hi/lo
// MODE 2/3: out = acc * scale -> fp32
#define BM 128
#define BN 128
#define BKt 32
#define TILE_STRIDE 80                       // bytes per 32-elem bf16 row (+16B pad)
#define SUB_BYTES (128*TILE_STRIDE)          // 10240 per sub-tile
#define STAGE_BYTES (4*SUB_BYTES)            // Ahi Alo Bhi Blo = 40960
#define GEMM_SMEM (2*STAGE_BYTES)            // 81920 -> 2 CTAs/SM

__device__ __forceinline__ void load_tile(
    uint32_t stbase,
    const __nv_bfloat16* pAh, const __nv_bfloat16* pAl,
    const __nv_bfloat16* pBh, const __nv_bfloat16* pBl,
    long long ldA, long long ldB, int k0, int tid)
{
#pragma unroll
    for (int t = 0; t < 2; t++) {
        int id = tid + t * 256;
        int r = id >> 2, c = id & 3;
        uint32_t doff = (uint32_t)r * TILE_STRIDE + c * 16;
        long long soA = (long long)r * ldA + k0 + c * 8;
        long long soB = (long long)r * ldB + k0 + c * 8;
        cpa16(stbase + doff,                 pAh + soA);
        cpa16(stbase + SUB_BYTES + doff,     pAl + soA);
        cpa16(stbase + 2*SUB_BYTES + doff,   pBh + soB);
        cpa16(stbase + 3*SUB_BYTES + doff,   pBl + soB);
    }
}

template<int MODE>
__global__ __launch_bounds__(256, 2) void mm_kernel(
    const __nv_bfloat16* __restrict__ Ahi, const __nv_bfloat16* __restrict__ Alo,
    long long ldA, long long strideA,
    const __nv_bfloat16* __restrict__ Bhi, const __nv_bfloat16* __restrict__ Blo,
    long long ldB, long long strideB,
    const float* __restrict__ bias,
    float* __restrict__ outF,
    __nv_bfloat16* __restrict__ outHi, __nv_bfloat16* __restrict__ outLo,
    long long ldC, long long strideC,
    int Ksz, float scale)
{
    extern __shared__ char smem[];
    const uint32_t sb = smem_u32(smem);
    const int tid = threadIdx.x;
    const int wid = tid >> 5, lane = tid & 31;
    const int wm = wid >> 2, wn = wid & 3;        // 2 x 4 warp grid
    const int g8 = lane & 7, quad = lane >> 3;
    const int g = lane >> 2, tg = lane & 3;

    const long long bz = blockIdx.z;
    const long long tileM = (long long)blockIdx.y * BM;
    const long long tileN = (long long)blockIdx.x * BN;
    const __nv_bfloat16* pAh = Ahi + bz * strideA + tileM * ldA;
    const __nv_bfloat16* pAl = Alo + bz * strideA + tileM * ldA;
    const __nv_bfloat16* pBh = Bhi + bz * strideB + tileN * ldB;
    const __nv_bfloat16* pBl = Blo + bz * strideB + tileN * ldB;

    float acc[4][4][4];
#pragma unroll
    for (int i = 0; i < 4; i++)
#pragma unroll
        for (int j = 0; j < 4; j++)
#pragma unroll
            for (int c = 0; c < 4; c++) acc[i][j][c] = 0.f;

    const int KT = Ksz / BKt;

    // prologue: both stages in flight
    load_tile(sb + 0*STAGE_BYTES, pAh, pAl, pBh, pBl, ldA, ldB, 0, tid);
    CP_COMMIT();
    load_tile(sb + 1*STAGE_BYTES, pAh, pAl, pBh, pBl, ldA, ldB, BKt, tid);
    CP_COMMIT();

    // per-thread ldmatrix base offsets (row-padded layout, stride 80B)
    const uint32_t aBase = (uint32_t)(wm*64 + g8 + ((quad & 1) ? 8 : 0)) * TILE_STRIDE
                         + ((quad & 2) ? 16 : 0);
    const uint32_t bBase = (uint32_t)(wn*32 + g8 + ((quad & 2) ? 8 : 0)) * TILE_STRIDE
                         + ((quad & 1) ? 16 : 0);

#pragma unroll 1
    for (int kt = 0; kt < KT; kt++) {
        if (kt < KT - 1) asm volatile("cp.async.wait_group 1;" ::: "memory");
        else             asm volatile("cp.async.wait_group 0;" ::: "memory");
        __syncthreads();
        const uint32_t base = sb + (kt & 1) * STAGE_BYTES;
#pragma unroll
        for (int ks = 0; ks < 2; ks++) {
            uint32_t ah[4][4], al[4][4], bh[2][4], bl[2][4];
#pragma unroll
            for (int i = 0; i < 4; i++)
                ldm4(ah[i], base + aBase + i * (16*TILE_STRIDE) + ks * 32);
#pragma unroll
            for (int j = 0; j < 2; j++)
                ldm4(bh[j], base + 2*SUB_BYTES + bBase + j * (16*TILE_STRIDE) + ks * 32);
            // hi * hi
#pragma unroll
            for (int i = 0; i < 4; i++)
#pragma unroll
                for (int j = 0; j < 4; j++)
                    mma16816(acc[i][j], ah[i], bh[j>>1][(j&1)*2], bh[j>>1][(j&1)*2+1]);
            // hi * lo
#pragma unroll
            for (int j = 0; j < 2; j++)
                ldm4(bl[j], base + 3*SUB_BYTES + bBase + j * (16*TILE_STRIDE) + ks * 32);
#pragma unroll
            for (int i = 0; i < 4; i++)
#pragma unroll
                for (int j = 0; j < 4; j++)
                    mma16816(acc[i][j], ah[i], bl[j>>1][(j&1)*2], bl[j>>1][(j&1)*2+1]);
            // lo * hi
#pragma unroll
            for (int i = 0; i < 4; i++)
                ldm4(al[i], base + SUB_BYTES + aBase + i * (16*TILE_STRIDE) + ks * 32);
#pragma unroll
            for (int i = 0; i < 4; i++)
#pragma unroll
                for (int j = 0; j < 4; j++)
                    mma16816(acc[i][j], al[i], bh[j>>1][(j&1)*2], bh[j>>1][(j&1)*2+1]);
        }
        if (kt + 2 < KT) {
            __syncthreads();   // all warps done reading this buffer before refill
            load_tile(base, pAh, pAl, pBh, pBl, ldA, ldB, (kt + 2) * BKt, tid);
            CP_COMMIT();
        }
    }

    // ---------------- epilogue ----------------
    const long long rowBase = tileM + wm * 64;
    const long long colBase = tileN + wn * 32;
    const long long cOff = bz * strideC;
#pragma unroll
    for (int i = 0; i < 4; i++) {
#pragma unroll
        for (int j = 0; j < 4; j++) {
            long long r0 = rowBase + i * 16 + g;
            long long c0 = colBase + j * 8 + 2 * tg;
#pragma unroll
            for (int h = 0; h < 2; h++) {
                long long r = r0 + h * 8;
                float f0 = acc[i][j][2*h + 0];
                float f1 = acc[i][j][2*h + 1];
                long long off = cOff + r * ldC + c0;
                if (MODE >= 2) {
                    float2 v; v.x = f0 * scale; v.y = f1 * scale;
                    *(float2*)(outF + off) = v;
                } else {
                    if (MODE == 0) { f0 += bias[c0]; f1 += bias[c0 + 1]; }
                    else           { float bb = bias[r]; f0 += bb; f1 += bb; }
                    __nv_bfloat16 h0 = __float2bfloat16(f0);
                    __nv_bfloat16 h1 = __float2bfloat16(f1);
                    __nv_bfloat16 l0 = __float2bfloat16(f0 - __bfloat162float(h0));
                    __nv_bfloat16 l1 = __float2bfloat16(f1 - __bfloat162float(h1));
                    uint32_t hp = (uint32_t)__bfloat16_as_ushort(h0) |
                                  ((uint32_t)__bfloat16_as_ushort(h1) << 16);
                    uint32_t lp = (uint32_t)__bfloat16_as_ushort(l0) |
                                  ((uint32_t)__bfloat16_as_ushort(l1) << 16);
                    *(uint32_t*)(outHi + off) = hp;
                    *(uint32_t*)(outLo + off) = lp;
                }
            }
        }
    }
}

// ---------------- split fp32 -> bf16 hi/lo ---------------------------------
__global__ __launch_bounds__(256) void split_kernel(
    const float4* __restrict__ src, uint2* __restrict__ hi, uint2* __restrict__ lo, int n4)
{
    int i = blockIdx.x * 256 + threadIdx.x;
    if (i >= n4) return;
    float4 v = src[i];
    float f[4] = {v.x, v.y, v.z, v.w};
    uint32_t hh[2], ll[2];
#pragma unroll
    for (int j = 0; j < 2; j++) {
        __nv_bfloat16 h0 = __float2bfloat16(f[2*j]);
        __nv_bfloat16 h1 = __float2bfloat16(f[2*j+1]);
        __nv_bfloat16 l0 = __float2bfloat16(f[2*j]   - __bfloat162float(h0));
        __nv_bfloat16 l1 = __float2bfloat16(f[2*j+1] - __bfloat162float(h1));
        hh[j] = (uint32_t)__bfloat16_as_ushort(h0) | ((uint32_t)__bfloat16_as_ushort(h1) << 16);
        ll[j] = (uint32_t)__bfloat16_as_ushort(l0) | ((uint32_t)__bfloat16_as_ushort(l1) << 16);
    }
    hi[i] = make_uint2(hh[0], hh[1]);
    lo[i] = make_uint2(ll[0], ll[1]);
}

// ---------------- softmax rows, in-place, + bf16 split ---------------------
__global__ __launch_bounds__(256) void softmax_split_kernel(
    float* __restrict__ att, __nv_bfloat16* __restrict__ ahi, __nv_bfloat16* __restrict__ alo)
{
    __shared__ float row[2048];
    __shared__ float red[8];
    const long long base = (long long)blockIdx.x * 2048;
    float* p = att + base;
    const int tid = threadIdx.x;

    float m = -3.0e38f;
    for (int i = tid; i < 2048; i += 256) { float v = p[i]; row[i] = v; m = fmaxf(m, v); }
#pragma unroll
    for (int o = 16; o > 0; o >>= 1) m = fmaxf(m, __shfl_xor_sync(0xffffffffu, m, o));
    if ((tid & 31) == 0) red[tid >> 5] = m;
    __syncthreads();
    m = red[0];
#pragma unroll
    for (int i = 1; i < 8; i++) m = fmaxf(m, red[i]);
    __syncthreads();

    float s = 0.f;
    for (int i = tid; i < 2048; i += 256) { float e = __expf(row[i] - m); row[i] = e; s += e; }
#pragma unroll
    for (int o = 16; o > 0; o >>= 1) s += __shfl_xor_sync(0xffffffffu, s, o);
    if ((tid & 31) == 0) red[tid >> 5] = s;
    __syncthreads();
    s = red[0];
#pragma unroll
    for (int i = 1; i < 8; i++) s += red[i];
    const float inv = 1.f / s;

    for (int i = tid; i < 2048; i += 256) {
        float v = row[i] * inv;
        p[i] = v;
        __nv_bfloat16 h = __float2bfloat16(v);
        ahi[base + i] = h;
        alo[base + i] = __float2bfloat16(v - __bfloat162float(h));
    }
}

// ---------------------------------------------------------------------------
extern "C" void kernel_launch(void* const* d_in, const int* in_sizes, int n_in,
                              void* d_out, int out_size)
{
    const float* X  = (const float*)d_in[0];
    const float* Wq = (const float*)d_in[1];
    const float* bq = (const float*)d_in[2];
    const float* Wk = (const float*)d_in[3];
    const float* bk = (const float*)d_in[4];
    const float* Wv = (const float*)d_in[5];
    const float* bv = (const float*)d_in[6];

    float* outp = (float*)d_out;                      // [4,2048,1024]
    float* att  = outp + 8388608ll;                   // [4,2048,2048]

    __nv_bfloat16 *Xhi, *Xlo, *Wqh, *Wql, *Wkh, *Wkl, *Wvh, *Wvl;
    __nv_bfloat16 *Qhi, *Qlo, *Khi, *Klo, *Vth, *Vtl, *Ahi, *Alo;
    cudaGetSymbolAddress((void**)&Xhi, g_Xhi);  cudaGetSymbolAddress((void**)&Xlo, g_Xlo);
    cudaGetSymbolAddress((void**)&Wqh, g_Wqhi); cudaGetSymbolAddress((void**)&Wql, g_Wqlo);
    cudaGetSymbolAddress((void**)&Wkh, g_Wkhi); cudaGetSymbolAddress((void**)&Wkl, g_Wklo);
    cudaGetSymbolAddress((void**)&Wvh, g_Wvhi); cudaGetSymbolAddress((void**)&Wvl, g_Wvlo);
    cudaGetSymbolAddress((void**)&Qhi, g_Qhi);  cudaGetSymbolAddress((void**)&Qlo, g_Qlo);
    cudaGetSymbolAddress((void**)&Khi, g_Khi);  cudaGetSymbolAddress((void**)&Klo, g_Klo);
    cudaGetSymbolAddress((void**)&Vth, g_Vthi); cudaGetSymbolAddress((void**)&Vtl, g_Vtlo);
    cudaGetSymbolAddress((void**)&Ahi, g_AThi); cudaGetSymbolAddress((void**)&Alo, g_ATlo);

    cudaFuncSetAttribute(mm_kernel<0>, cudaFuncAttributeMaxDynamicSharedMemorySize, GEMM_SMEM);
    cudaFuncSetAttribute(mm_kernel<1>, cudaFuncAttributeMaxDynamicSharedMemorySize, GEMM_SMEM);
    cudaFuncSetAttribute(mm_kernel<2>, cudaFuncAttributeMaxDynamicSharedMemorySize, GEMM_SMEM);
    cudaFuncSetAttribute(mm_kernel<3>, cudaFuncAttributeMaxDynamicSharedMemorySize, GEMM_SMEM);

    // 1) split inputs to bf16 hi/lo
    split_kernel<<<8192, 256>>>((const float4*)X,  (uint2*)Xhi, (uint2*)Xlo, 2097152);
    split_kernel<<<1024, 256>>>((const float4*)Wq, (uint2*)Wqh, (uint2*)Wql, 262144);
    split_kernel<<<1024, 256>>>((const float4*)Wk, (uint2*)Wkh, (uint2*)Wkl, 262144);
    split_kernel<<<1024, 256>>>((const float4*)Wv, (uint2*)Wvh, (uint2*)Wvl, 262144);

    // 2) Q = X Wq^T + bq ; K = X Wk^T + bk   (M=8192, N=1024, K=1024)
    mm_kernel<0><<<dim3(8, 64, 1), 256, GEMM_SMEM>>>(
        Xhi, Xlo, 1024, 0, Wqh, Wql, 1024, 0, bq,
        nullptr, Qhi, Qlo, 1024, 0, 1024, 1.f);
    mm_kernel<0><<<dim3(8, 64, 1), 256, GEMM_SMEM>>>(
        Xhi, Xlo, 1024, 0, Wkh, Wkl, 1024, 0, bk,
        nullptr, Khi, Klo, 1024, 0, 1024, 1.f);

    // 3) V^T = Wv X^T + bv(row)   (M=1024 channels, N=8192 tokens, K=1024)
    mm_kernel<1><<<dim3(64, 8, 1), 256, GEMM_SMEM>>>(
        Wvh, Wvl, 1024, 0, Xhi, Xlo, 1024, 0, bv,
        nullptr, Vth, Vtl, 8192, 0, 1024, 1.f);

    // 4) scores = scale * Q K^T   (per batch: M=N=2048, K=1024) -> att fp32
    mm_kernel<2><<<dim3(16, 16, 4), 256, GEMM_SMEM>>>(
        Qhi, Qlo, 1024, 2097152ll, Khi, Klo, 1024, 2097152ll, nullptr,
        att, nullptr, nullptr, 2048, 4194304ll, 1024, SCALE_);

    // 5) softmax in place + bf16 split of attention
    softmax_split_kernel<<<8192, 256>>>(att, Ahi, Alo);

    // 6) out = att @ V  via  B = V^T  (per batch: M=2048, N=1024, K=2048)
    mm_kernel<3><<<dim3(8, 16, 4), 256, GEMM_SMEM>>>(
        Ahi, Alo, 2048, 4194304ll, Vth, Vtl, 8192, 2048ll, nullptr,
        outp, nullptr, nullptr, 1024, 2097152ll, 2048, 1.f);
}

// round 5
// speedup vs baseline: 2.8630x; 1.0170x over previous
#include <cuda_runtime.h>
#include <cuda_bf16.h>
#include <cstdint>

#define SCALE_ 0.03125f   // 1/sqrt(1024)

// ---------------- bf16-split scratch (device globals; no allocation) -------
__device__ __nv_bfloat16 g_Xhi[8192*1024];
__device__ __nv_bfloat16 g_Xlo[8192*1024];
__device__ __nv_bfloat16 g_Wqhi[1024*1024];
__device__ __nv_bfloat16 g_Wqlo[1024*1024];
__device__ __nv_bfloat16 g_Wkhi[1024*1024];
__device__ __nv_bfloat16 g_Wklo[1024*1024];
__device__ __nv_bfloat16 g_Wvhi[1024*1024];
__device__ __nv_bfloat16 g_Wvlo[1024*1024];
__device__ __nv_bfloat16 g_Qhi[8192*1024];
__device__ __nv_bfloat16 g_Qlo[8192*1024];
__device__ __nv_bfloat16 g_Khi[8192*1024];
__device__ __nv_bfloat16 g_Klo[8192*1024];
__device__ __nv_bfloat16 g_Vthi[1024*8192];   // V^T: [C, B*N]
__device__ __nv_bfloat16 g_Vtlo[1024*8192];
__device__ __nv_bfloat16 g_AThi[16777216];    // attention split [B,N,N]
__device__ __nv_bfloat16 g_ATlo[16777216];

// ---------------- PTX helpers ----------------------------------------------
__device__ __forceinline__ uint32_t smem_u32(const void* p) {
    uint32_t a;
    asm("{ .reg .u64 t; cvta.to.shared.u64 t, %1; cvt.u32.u64 %0, t; }"
        : "=r"(a) : "l"(p));
    return a;
}

__device__ __forceinline__ void cpa16(uint32_t dst, const void* src) {
    asm volatile("cp.async.cg.shared.global [%0], [%1], 16;" :: "r"(dst), "l"(src));
}
#define CP_COMMIT() asm volatile("cp.async.commit_group;" ::: "memory")

__device__ __forceinline__ void ldm4(uint32_t* r, uint32_t a) {
    asm volatile("ldmatrix.sync.aligned.m8n8.x4.shared.b16 {%0,%1,%2,%3}, [%4];"
        : "=r"(r[0]), "=r"(r[1]), "=r"(r[2]), "=r"(r[3]) : "r"(a));
}

__device__ __forceinline__ void mma16816(float* d, const uint32_t* a,
                                         uint32_t b0, uint32_t b1) {
    asm volatile(
        "mma.sync.aligned.m16n8k16.row.col.f32.bf16.bf16.f32 "
        "{%0,%1,%2,%3}, {%4,%5,%6,%7}, {%8,%9}, {%0,%1,%2,%3};"
        : "+f"(d[0]), "+f"(d[1]), "+f"(d[2]), "+f"(d[3])
        : "r"(a[0]), "r"(a[1]), "r"(a[2]), "r"(a[3]), "r"(b0), "r"(b1));
}

// ---------------- GEMM kernel ----------------------------------------------
// C[m,n] = sum_k A[m,k]*B[n,k]  (NT, 3-pass bf16 split). CTA tile 128x128,
// BK=32, 4 warps (warp tile 64x64), 2-stage cp.async, 2 CTAs/SM.
// MODE 0: out = acc + bias[n] -> bf16 hi/lo
// MODE 1: out = acc + bias[m] -> bf16 hi/lo
// MODE 2/3: out = acc * scale -> fp32
#define BM 128
#define BN 128
#define BKt 32
#define TILE_STRIDE 80                       // bytes per 32-elem bf16 row (+16B pad)
#define SUB_BYTES (128*TILE_STRIDE)          // 10240 per sub-tile
#define STAGE_BYTES (4*SUB_BYTES)            // Ahi Alo Bhi Blo = 40960
#define GEMM_SMEM (2*STAGE_BYTES)            // 81920 -> 2 CTAs/SM

__device__ __forceinline__ void load_tile(
    uint32_t stbase,
    const __nv_bfloat16* pAh, const __nv_bfloat16* pAl,
    const __nv_bfloat16* pBh, const __nv_bfloat16* pBl,
    long long ldA, long long ldB, int k0, int tid)
{
#pragma unroll
    for (int t = 0; t < 4; t++) {
        int id = tid + t * 128;
        int r = id >> 2, c = id & 3;
        uint32_t doff = (uint32_t)r * TILE_STRIDE + c * 16;
        long long soA = (long long)r * ldA + k0 + c * 8;
        long long soB = (long long)r * ldB + k0 + c * 8;
        cpa16(stbase + doff,                 pAh + soA);
        cpa16(stbase + SUB_BYTES + doff,     pAl + soA);
        cpa16(stbase + 2*SUB_BYTES + doff,   pBh + soB);
        cpa16(stbase + 3*SUB_BYTES + doff,   pBl + soB);
    }
}

template<int MODE>
__global__ __launch_bounds__(128, 2) void mm_kernel(
    const __nv_bfloat16* __restrict__ Ahi, const __nv_bfloat16* __restrict__ Alo,
    long long ldA, long long strideA,
    const __nv_bfloat16* __restrict__ Bhi, const __nv_bfloat16* __restrict__ Blo,
    long long ldB, long long strideB,
    const float* __restrict__ bias,
    float* __restrict__ outF,
    __nv_bfloat16* __restrict__ outHi, __nv_bfloat16* __restrict__ outLo,
    long long ldC, long long strideC,
    int Ksz, float scale)
{
    extern __shared__ char smem[];
    const uint32_t sb = smem_u32(smem);
    const int tid = threadIdx.x;
    const int wid = tid >> 5, lane = tid & 31;
    const int wm = wid >> 1, wn = wid & 1;        // 2 x 2 warp grid, 64x64 tiles
    const int g8 = lane & 7, quad = lane >> 3;
    const int g = lane >> 2, tg = lane & 3;

    const long long bz = blockIdx.z;
    const long long tileM = (long long)blockIdx.y * BM;
    const long long tileN = (long long)blockIdx.x * BN;
    const __nv_bfloat16* pAh = Ahi + bz * strideA + tileM * ldA;
    const __nv_bfloat16* pAl = Alo + bz * strideA + tileM * ldA;
    const __nv_bfloat16* pBh = Bhi + bz * strideB + tileN * ldB;
    const __nv_bfloat16* pBl = Blo + bz * strideB + tileN * ldB;

    float acc[4][8][4];
#pragma unroll
    for (int i = 0; i < 4; i++)
#pragma unroll
        for (int j = 0; j < 8; j++)
#pragma unroll
            for (int c = 0; c < 4; c++) acc[i][j][c] = 0.f;

    const int KT = Ksz / BKt;

    // prologue: both stages in flight
    load_tile(sb + 0*STAGE_BYTES, pAh, pAl, pBh, pBl, ldA, ldB, 0, tid);
    CP_COMMIT();
    load_tile(sb + 1*STAGE_BYTES, pAh, pAl, pBh, pBl, ldA, ldB, BKt, tid);
    CP_COMMIT();

    // per-thread ldmatrix base offsets (row-padded layout, stride 80B)
    const uint32_t aBase = (uint32_t)(wm*64 + g8 + ((quad & 1) ? 8 : 0)) * TILE_STRIDE
                         + ((quad & 2) ? 16 : 0);
    const uint32_t bBase = (uint32_t)(wn*64 + g8 + ((quad & 2) ? 8 : 0)) * TILE_STRIDE
                         + ((quad & 1) ? 16 : 0);

#pragma unroll 1
    for (int kt = 0; kt < KT; kt++) {
        if (kt < KT - 1) asm volatile("cp.async.wait_group 1;" ::: "memory");
        else             asm volatile("cp.async.wait_group 0;" ::: "memory");
        __syncthreads();
        const uint32_t base = sb + (kt & 1) * STAGE_BYTES;
#pragma unroll
        for (int ks = 0; ks < 2; ks++) {
            uint32_t ah[4][4], bh[4][4], tf[4][4];
#pragma unroll
            for (int i = 0; i < 4; i++)
                ldm4(ah[i], base + aBase + i * (16*TILE_STRIDE) + ks * 32);
#pragma unroll
            for (int j = 0; j < 4; j++)
                ldm4(bh[j], base + 2*SUB_BYTES + bBase + j * (16*TILE_STRIDE) + ks * 32);
            // pass 1: hi * hi
#pragma unroll
            for (int i = 0; i < 4; i++)
#pragma unroll
                for (int j = 0; j < 8; j++)
                    mma16816(acc[i][j], ah[i], bh[j>>1][(j&1)*2], bh[j>>1][(j&1)*2+1]);
            // pass 2: hi * lo   (tf = B lo)
#pragma unroll
            for (int j = 0; j < 4; j++)
                ldm4(tf[j], base + 3*SUB_BYTES + bBase + j * (16*TILE_STRIDE) + ks * 32);
#pragma unroll
            for (int i = 0; i < 4; i++)
#pragma unroll
                for (int j = 0; j < 8; j++)
                    mma16816(acc[i][j], ah[i], tf[j>>1][(j&1)*2], tf[j>>1][(j&1)*2+1]);
            // pass 3: lo * hi   (tf = A lo)
#pragma unroll
            for (int i = 0; i < 4; i++)
                ldm4(tf[i], base + SUB_BYTES + aBase + i * (16*TILE_STRIDE) + ks * 32);
#pragma unroll
            for (int i = 0; i < 4; i++)
#pragma unroll
                for (int j = 0; j < 8; j++)
                    mma16816(acc[i][j], tf[i], bh[j>>1][(j&1)*2], bh[j>>1][(j&1)*2+1]);
        }
        if (kt + 2 < KT) {
            __syncthreads();   // all warps done reading this buffer before refill
            load_tile(base, pAh, pAl, pBh, pBl, ldA, ldB, (kt + 2) * BKt, tid);
            CP_COMMIT();
        }
    }

    // ---------------- epilogue ----------------
    const long long rowBase = tileM + wm * 64;
    const long long colBase = tileN + wn * 64;
    const long long cOff = bz * strideC;
#pragma unroll
    for (int i = 0; i < 4; i++) {
#pragma unroll
        for (int j = 0; j < 8; j++) {
            long long r0 = rowBase + i * 16 + g;
            long long c0 = colBase + j * 8 + 2 * tg;
#pragma unroll
            for (int h = 0; h < 2; h++) {
                long long r = r0 + h * 8;
                float f0 = acc[i][j][2*h + 0];
                float f1 = acc[i][j][2*h + 1];
                long long off = cOff + r * ldC + c0;
                if (MODE >= 2) {
                    float2 v; v.x = f0 * scale; v.y = f1 * scale;
                    *(float2*)(outF + off) = v;
                } else {
                    if (MODE == 0) { f0 += bias[c0]; f1 += bias[c0 + 1]; }
                    else           { float bb = bias[r]; f0 += bb; f1 += bb; }
                    __nv_bfloat16 h0 = __float2bfloat16(f0);
                    __nv_bfloat16 h1 = __float2bfloat16(f1);
                    __nv_bfloat16 l0 = __float2bfloat16(f0 - __bfloat162float(h0));
                    __nv_bfloat16 l1 = __float2bfloat16(f1 - __bfloat162float(h1));
                    uint32_t hp = (uint32_t)__bfloat16_as_ushort(h0) |
                                  ((uint32_t)__bfloat16_as_ushort(h1) << 16);
                    uint32_t lp = (uint32_t)__bfloat16_as_ushort(l0) |
                                  ((uint32_t)__bfloat16_as_ushort(l1) << 16);
                    *(uint32_t*)(outHi + off) = hp;
                    *(uint32_t*)(outLo + off) = lp;
                }
            }
        }
    }
}

// ---------------- split fp32 -> bf16 hi/lo ---------------------------------
__global__ __launch_bounds__(256) void split_kernel(
    const float4* __restrict__ src, uint2* __restrict__ hi, uint2* __restrict__ lo, int n4)
{
    int i = blockIdx.x * 256 + threadIdx.x;
    if (i >= n4) return;
    float4 v = src[i];
    float f[4] = {v.x, v.y, v.z, v.w};
    uint32_t hh[2], ll[2];
#pragma unroll
    for (int j = 0; j < 2; j++) {
        __nv_bfloat16 h0 = __float2bfloat16(f[2*j]);
        __nv_bfloat16 h1 = __float2bfloat16(f[2*j+1]);
        __nv_bfloat16 l0 = __float2bfloat16(f[2*j]   - __bfloat162float(h0));
        __nv_bfloat16 l1 = __float2bfloat16(f[2*j+1] - __bfloat162float(h1));
        hh[j] = (uint32_t)__bfloat16_as_ushort(h0) | ((uint32_t)__bfloat16_as_ushort(h1) << 16);
        ll[j] = (uint32_t)__bfloat16_as_ushort(l0) | ((uint32_t)__bfloat16_as_ushort(l1) << 16);
    }
    hi[i] = make_uint2(hh[0], hh[1]);
    lo[i] = make_uint2(ll[0], ll[1]);
}

// ---------------- softmax rows, in-place, + bf16 split ---------------------
__global__ __launch_bounds__(256) void softmax_split_kernel(
    float* __restrict__ att, __nv_bfloat16* __restrict__ ahi, __nv_bfloat16* __restrict__ alo)
{
    __shared__ float row[2048];
    __shared__ float red[8];
    const long long base = (long long)blockIdx.x * 2048;
    float* p = att + base;
    const int tid = threadIdx.x;

    float m = -3.0e38f;
    for (int i = tid; i < 2048; i += 256) { float v = p[i]; row[i] = v; m = fmaxf(m, v); }
#pragma unroll
    for (int o = 16; o > 0; o >>= 1) m = fmaxf(m, __shfl_xor_sync(0xffffffffu, m, o));
    if ((tid & 31) == 0) red[tid >> 5] = m;
    __syncthreads();
    m = red[0];
#pragma unroll
    for (int i = 1; i < 8; i++) m = fmaxf(m, red[i]);
    __syncthreads();

    float s = 0.f;
    for (int i = tid; i < 2048; i += 256) { float e = __expf(row[i] - m); row[i] = e; s += e; }
#pragma unroll
    for (int o = 16; o > 0; o >>= 1) s += __shfl_xor_sync(0xffffffffu, s, o);
    if ((tid & 31) == 0) red[tid >> 5] = s;
    __syncthreads();
    s = red[0];
#pragma unroll
    for (int i = 1; i < 8; i++) s += red[i];
    const float inv = 1.f / s;

    for (int i = tid; i < 2048; i += 256) {
        float v = row[i] * inv;
        p[i] = v;
        __nv_bfloat16 h = __float2bfloat16(v);
        ahi[base + i] = h;
        alo[base + i] = __float2bfloat16(v - __bfloat162float(h));
    }
}

// ---------------------------------------------------------------------------
extern "C" void kernel_launch(void* const* d_in, const int* in_sizes, int n_in,
                              void* d_out, int out_size)
{
    const float* X  = (const float*)d_in[0];
    const float* Wq = (const float*)d_in[1];
    const float* bq = (const float*)d_in[2];
    const float* Wk = (const float*)d_in[3];
    const float* bk = (const float*)d_in[4];
    const float* Wv = (const float*)d_in[5];
    const float* bv = (const float*)d_in[6];

    float* outp = (float*)d_out;                      // [4,2048,1024]
    float* att  = outp + 8388608ll;                   // [4,2048,2048]

    __nv_bfloat16 *Xhi, *Xlo, *Wqh, *Wql, *Wkh, *Wkl, *Wvh, *Wvl;
    __nv_bfloat16 *Qhi, *Qlo, *Khi, *Klo, *Vth, *Vtl, *Ahi, *Alo;
    cudaGetSymbolAddress((void**)&Xhi, g_Xhi);  cudaGetSymbolAddress((void**)&Xlo, g_Xlo);
    cudaGetSymbolAddress((void**)&Wqh, g_Wqhi); cudaGetSymbolAddress((void**)&Wql, g_Wqlo);
    cudaGetSymbolAddress((void**)&Wkh, g_Wkhi); cudaGetSymbolAddress((void**)&Wkl, g_Wklo);
    cudaGetSymbolAddress((void**)&Wvh, g_Wvhi); cudaGetSymbolAddress((void**)&Wvl, g_Wvlo);
    cudaGetSymbolAddress((void**)&Qhi, g_Qhi);  cudaGetSymbolAddress((void**)&Qlo, g_Qlo);
    cudaGetSymbolAddress((void**)&Khi, g_Khi);  cudaGetSymbolAddress((void**)&Klo, g_Klo);
    cudaGetSymbolAddress((void**)&Vth, g_Vthi); cudaGetSymbolAddress((void**)&Vtl, g_Vtlo);
    cudaGetSymbolAddress((void**)&Ahi, g_AThi); cudaGetSymbolAddress((void**)&Alo, g_ATlo);

    cudaFuncSetAttribute(mm_kernel<0>, cudaFuncAttributeMaxDynamicSharedMemorySize, GEMM_SMEM);
    cudaFuncSetAttribute(mm_kernel<1>, cudaFuncAttributeMaxDynamicSharedMemorySize, GEMM_SMEM);
    cudaFuncSetAttribute(mm_kernel<2>, cudaFuncAttributeMaxDynamicSharedMemorySize, GEMM_SMEM);
    cudaFuncSetAttribute(mm_kernel<3>, cudaFuncAttributeMaxDynamicSharedMemorySize, GEMM_SMEM);

    // 1) split inputs to bf16 hi/lo
    split_kernel<<<8192, 256>>>((const float4*)X,  (uint2*)Xhi, (uint2*)Xlo, 2097152);
    split_kernel<<<1024, 256>>>((const float4*)Wq, (uint2*)Wqh, (uint2*)Wql, 262144);
    split_kernel<<<1024, 256>>>((const float4*)Wk, (uint2*)Wkh, (uint2*)Wkl, 262144);
    split_kernel<<<1024, 256>>>((const float4*)Wv, (uint2*)Wvh, (uint2*)Wvl, 262144);

    // 2) Q = X Wq^T + bq ; K = X Wk^T + bk   (M=8192, N=1024, K=1024)
    mm_kernel<0><<<dim3(8, 64, 1), 128, GEMM_SMEM>>>(
        Xhi, Xlo, 1024, 0, Wqh, Wql, 1024, 0, bq,
        nullptr, Qhi, Qlo, 1024, 0, 1024, 1.f);
    mm_kernel<0><<<dim3(8, 64, 1), 128, GEMM_SMEM>>>(
        Xhi, Xlo, 1024, 0, Wkh, Wkl, 1024, 0, bk,
        nullptr, Khi, Klo, 1024, 0, 1024, 1.f);

    // 3) V^T = Wv X^T + bv(row)   (M=1024 channels, N=8192 tokens, K=1024)
    mm_kernel<1><<<dim3(64, 8, 1), 128, GEMM_SMEM>>>(
        Wvh, Wvl, 1024, 0, Xhi, Xlo, 1024, 0, bv,
        nullptr, Vth, Vtl, 8192, 0, 1024, 1.f);

    // 4) scores = scale * Q K^T   (per batch: M=N=2048, K=1024) -> att fp32
    mm_kernel<2><<<dim3(16, 16, 4), 128, GEMM_SMEM>>>(
        Qhi, Qlo, 1024, 2097152ll, Khi, Klo, 1024, 2097152ll, nullptr,
        att, nullptr, nullptr, 2048, 4194304ll, 1024, SCALE_);

    // 5) softmax in place + bf16 split of attention
    softmax_split_kernel<<<8192, 256>>>(att, Ahi, Alo);

    // 6) out = att @ V  via  B = V^T  (per batch: M=2048, N=1024, K=2048)
    mm_kernel<3><<<dim3(8, 16, 4), 128, GEMM_SMEM>>>(
        Ahi, Alo, 2048, 4194304ll, Vth, Vtl, 8192, 2048ll, nullptr,
        outp, nullptr, nullptr, 1024, 2097152ll, 2048, 1.f);
}